// round 8
// baseline (speedup 1.0000x reference)
#include <cuda_runtime.h>
#include <cuda_bf16.h>

// PointPillarsScatter gather v7:
//  v5 layout (byte-packed counts, 4 cells x 4 channels per thread, STG.128)
//  + ZERO-FIRST stores: every thread stores zeros to its output lines IMMEDIATELY
//    (no data dependency -> the 268MB write stream issues at full LSU/DRAM rate),
//    then loads counts and, only for occupied cell groups (~37%), overwrites the
//    same addresses with the gathered sums. Same-thread same-address ordering is
//    guaranteed; the overwrite hits the still-L2-resident line, so DRAM sees ~one
//    writeback per line.
//
// Inputs:
//   d_in[0]: pillar_feats  float32 [B=4, P=30000, C=64]
//   d_in[1]: pillar_coords int32   [B=4, P=30000, 2]  (y, x)
// Output: float32 [4, 64, 512, 512]

#define BEV_H 512
#define BEV_W 512
#define HW (BEV_H * BEV_W)      // 262144 = 2^18
#define C_DIM 64
#define P_DIM 30000
#define B_DIM 4
#define CAP 8
#define NGRP ((B_DIM * HW) / 4) // 262144 cell groups (4 cells each)

__device__ unsigned int   d_count[NGRP];              // 1 MB: 4 x u8 counts per word
__device__ unsigned short d_list[B_DIM * HW * CAP];   // 16 MB

__global__ void pp_build_kernel(const int* __restrict__ coords) {
    int p = blockIdx.x * blockDim.x + threadIdx.x;
    if (p >= B_DIM * P_DIM) return;

    int2 yx = reinterpret_cast<const int2*>(coords)[p];
    int y = min(max(yx.x, 0), BEV_H - 1);
    int x = min(max(yx.y, 0), BEV_W - 1);

    int b   = p / P_DIM;
    int pid = p - b * P_DIM;
    int idx = b * HW + y * BEV_W + x;

    unsigned shift = (idx & 3) * 8;
    unsigned old = atomicAdd(&d_count[idx >> 2], 1u << shift);
    unsigned pos = (old >> shift) & 0xFFu;
    if (pos < CAP) d_list[(size_t)idx * CAP + pos] = (unsigned short)pid;
}

__global__ __launch_bounds__(256) void pp_gather_kernel(const float* __restrict__ feats,
                                                        float* __restrict__ out) {
    int tid = blockIdx.x * blockDim.x + threadIdx.x;  // 0 .. 16*NGRP
    int grp = tid & (NGRP - 1);     // cell group (consecutive across warp -> coalesced)
    int chg = tid >> 18;            // channel group 0..15 (4 channels each)

    int idx0  = grp << 2;           // first cell index (b*HW + cell)
    int b     = idx0 >> 18;
    int cell0 = idx0 & (HW - 1);

    float* o = out + ((size_t)b * C_DIM + (size_t)(chg << 2)) * HW + cell0;

    // ---- Phase 0: dependency-free zero stores (bulk write stream at full rate) ----
    const float4 zero4 = make_float4(0.f, 0.f, 0.f, 0.f);
    #pragma unroll
    for (int c = 0; c < 4; c++)
        *reinterpret_cast<float4*>(o + (size_t)c * HW) = zero4;

    // ---- Phase 1: counts; only occupied groups do any further work ----
    unsigned cw = d_count[grp];     // 4 packed counts, L2 hit
    if (cw == 0) return;            // 63% of threads exit here

    float acc[4][4];
    #pragma unroll
    for (int ci = 0; ci < 4; ci++)
        #pragma unroll
        for (int c = 0; c < 4; c++) acc[ci][c] = 0.0f;

    const float* fb = feats + (size_t)b * P_DIM * C_DIM + (chg << 2);
    const unsigned short* lst = &d_list[(size_t)idx0 * CAP];
    #pragma unroll
    for (int ci = 0; ci < 4; ci++) {
        int n = (int)((cw >> (ci * 8)) & 0xFFu);
        n = min(n, CAP);
        for (int i = 0; i < n; i++) {
            unsigned pid = lst[ci * CAP + i];      // u16 L2/L1 hit
            float4 v = *reinterpret_cast<const float4*>(fb + (size_t)pid * C_DIM);
            acc[ci][0] += v.x; acc[ci][1] += v.y; acc[ci][2] += v.z; acc[ci][3] += v.w;
        }
    }

    // ---- Phase 2: overwrite the (L2-resident) zero lines with the real sums ----
    #pragma unroll
    for (int c = 0; c < 4; c++) {
        float4 v = make_float4(acc[0][c], acc[1][c], acc[2][c], acc[3][c]);
        *reinterpret_cast<float4*>(o + (size_t)c * HW) = v;
    }
}

extern "C" void kernel_launch(void* const* d_in, const int* in_sizes, int n_in,
                              void* d_out, int out_size) {
    const float* feats  = (const float*)d_in[0];
    const int*   coords = (const int*)d_in[1];
    float*       out    = (float*)d_out;

    // Zero the packed counters (1 MB, graph-capturable, ~1us)
    void* count_ptr = nullptr;
    cudaGetSymbolAddress(&count_ptr, d_count);
    cudaMemsetAsync(count_ptr, 0, NGRP * sizeof(unsigned int));

    int n_pillars = B_DIM * P_DIM;                 // 120,000
    pp_build_kernel<<<(n_pillars + 255) / 256, 256>>>(coords);

    int n_threads = 16 * NGRP;                     // 4,194,304
    pp_gather_kernel<<<n_threads / 256, 256>>>(feats, out);
}

// round 9
// speedup vs baseline: 1.3304x; 1.3304x over previous
#include <cuda_runtime.h>
#include <cuda_bf16.h>

// PointPillarsScatter gather v8 (R6 structure + fused count|pid cell word):
//  - d_cellinfo[cell] = (n << 24) | sum(pids). For n==1 (94.5% of occupied cells)
//    the low bits ARE the pillar id -> gather needs ONE L2 load before its feats load.
//  - n>=2 cells (0.65%) fall back to the u16 side list.
//  - thread = 4 consecutive cells x 4 channels; all stores full-warp STG.128 __stcs.
//
// Inputs:
//   d_in[0]: pillar_feats  float32 [B=4, P=30000, C=64]
//   d_in[1]: pillar_coords int32   [B=4, P=30000, 2]  (y, x)
// Output: float32 [4, 64, 512, 512]

#define BEV_H 512
#define BEV_W 512
#define HW (BEV_H * BEV_W)      // 262144 = 2^18
#define C_DIM 64
#define P_DIM 30000
#define B_DIM 4
#define CAP 8
#define NGRP ((B_DIM * HW) / 4) // 262144 cell groups (4 cells each)

__device__ unsigned int   d_cellinfo[B_DIM * HW];     // 4 MB: (count<<24) | sum(pid)
__device__ unsigned short d_list[B_DIM * HW * CAP];   // 16 MB side lists (n>=2 only)

__global__ void pp_build_kernel(const int* __restrict__ coords) {
    int p = blockIdx.x * blockDim.x + threadIdx.x;
    if (p >= B_DIM * P_DIM) return;

    int2 yx = reinterpret_cast<const int2*>(coords)[p];
    int y = min(max(yx.x, 0), BEV_H - 1);
    int x = min(max(yx.y, 0), BEV_W - 1);

    int b   = p / P_DIM;
    int pid = p - b * P_DIM;
    int idx = b * HW + y * BEV_W + x;

    unsigned old = atomicAdd(&d_cellinfo[idx], (1u << 24) | (unsigned)pid);
    unsigned pos = old >> 24;
    if (pos < CAP) d_list[(size_t)idx * CAP + pos] = (unsigned short)pid;
}

__global__ __launch_bounds__(256) void pp_gather_kernel(const float* __restrict__ feats,
                                                        float* __restrict__ out) {
    int tid = blockIdx.x * blockDim.x + threadIdx.x;  // 0 .. 16*NGRP
    int grp = tid & (NGRP - 1);     // cell group (consecutive across warp -> coalesced)
    int chg = tid >> 18;            // channel group 0..15 (4 channels each)

    int idx0  = grp << 2;           // first cell index (b*HW + cell)
    int b     = idx0 >> 18;
    int cell0 = idx0 & (HW - 1);

    // One coalesced 16B load: count + first-pid for all 4 cells (4MB L2-resident)
    uint4 wv = *reinterpret_cast<const uint4*>(&d_cellinfo[idx0]);
    unsigned w[4] = {wv.x, wv.y, wv.z, wv.w};

    float acc[4][4];
    #pragma unroll
    for (int ci = 0; ci < 4; ci++)
        #pragma unroll
        for (int c = 0; c < 4; c++) acc[ci][c] = 0.0f;

    const float* fb = feats + (size_t)b * P_DIM * C_DIM + (chg << 2);

    #pragma unroll
    for (int ci = 0; ci < 4; ci++) {
        unsigned n = w[ci] >> 24;
        if (n == 0) continue;                     // ~89% of cells
        if (n == 1) {                             // 94.5% of occupied: pid is in the word
            unsigned pid = w[ci] & 0xFFFFFFu;
            float4 v = *reinterpret_cast<const float4*>(fb + (size_t)pid * C_DIM);
            acc[ci][0] += v.x; acc[ci][1] += v.y; acc[ci][2] += v.z; acc[ci][3] += v.w;
        } else {                                  // rare: side list
            int m = min((int)n, CAP);
            const unsigned short* lst = &d_list[(size_t)(idx0 + ci) * CAP];
            for (int i = 0; i < m; i++) {
                unsigned pid = lst[i];
                float4 v = *reinterpret_cast<const float4*>(fb + (size_t)pid * C_DIM);
                acc[ci][0] += v.x; acc[ci][1] += v.y; acc[ci][2] += v.z; acc[ci][3] += v.w;
            }
        }
    }

    float* o = out + ((size_t)b * C_DIM + (size_t)(chg << 2)) * HW + cell0;
    #pragma unroll
    for (int c = 0; c < 4; c++) {
        float4 v = make_float4(acc[0][c], acc[1][c], acc[2][c], acc[3][c]);
        __stcs(reinterpret_cast<float4*>(o + (size_t)c * HW), v);
    }
}

extern "C" void kernel_launch(void* const* d_in, const int* in_sizes, int n_in,
                              void* d_out, int out_size) {
    const float* feats  = (const float*)d_in[0];
    const int*   coords = (const int*)d_in[1];
    float*       out    = (float*)d_out;

    // Zero the fused cell words (4 MB, graph-capturable)
    void* info_ptr = nullptr;
    cudaGetSymbolAddress(&info_ptr, d_cellinfo);
    cudaMemsetAsync(info_ptr, 0, (size_t)B_DIM * HW * sizeof(unsigned int));

    int n_pillars = B_DIM * P_DIM;                 // 120,000
    pp_build_kernel<<<(n_pillars + 255) / 256, 256>>>(coords);

    int n_threads = 16 * NGRP;                     // 4,194,304
    pp_gather_kernel<<<n_threads / 256, 256>>>(feats, out);
}